// round 15
// baseline (speedup 1.0000x reference)
#include <cuda_runtime.h>
#include <cuda_bf16.h>
#include <cstdint>

#define NROWS 8192
#define DIM   512
#define BM    128
#define BN    128
#define BK    32
#define NK    (DIM / BK)          // 16 k-chunks
#define STAGES 3
// Fragment-permuted tiles:
//  A: [rb(16 rows)][kb(8 k)] tile of 128 floats, lane-major, 4 elems/lane contiguous
//  B: [nb(8 cols)][kb(8 k)] tile of 64 floats, lane-major, 2 elems/lane contiguous
#define A_STAGE_F 4096            // 8 rb * 4 kb * 128
#define B_STAGE_F 4096            // 16 nb * 4 kb * 64
#define STAGE_F   (A_STAGE_F + B_STAGE_F)
#define SMEM_BYTES (STAGES * STAGE_F * 4)   // 98304

// ---------------- device scratch (static, allocation-free) ----------------
__device__ float g_s32[NROWS * DIM];   // tf32-rounded s, A-fragment-permuted [512 rb][64 kb][128]
__device__ float g_t32[NROWS * DIM];   // tf32-rounded t, B-fragment-permuted [1024 nb][64 kb][64]
__device__ float g_s_sq[NROWS];
__device__ float g_t_sq[NROWS];

// ---------------- helpers ----------------
__device__ __forceinline__ uint32_t smem_u32(const void* p) {
    uint32_t a;
    asm("{ .reg .u64 t; cvta.to.shared.u64 t, %1; cvt.u32.u64 %0, t; }"
        : "=r"(a) : "l"(p));
    return a;
}

__device__ __forceinline__ float tf32_round(float x) {
    uint32_t u;
    asm("cvt.rna.tf32.f32 %0, %1;" : "=r"(u) : "f"(x));
    return __uint_as_float(u);
}

#define CP_ASYNC16(smem_addr, gptr)                                           \
    asm volatile("cp.async.cg.shared.global [%0], [%1], 16;"                  \
                 :: "r"(smem_addr), "l"(gptr) : "memory")
#define CP_COMMIT() asm volatile("cp.async.commit_group;" ::: "memory")

__device__ __forceinline__ void mma_tf32(float* d, const uint32_t* a,
                                         const uint32_t* b) {
    asm volatile(
        "mma.sync.aligned.m16n8k8.row.col.f32.tf32.tf32.f32 "
        "{%0,%1,%2,%3}, {%4,%5,%6,%7}, {%8,%9}, {%0,%1,%2,%3};"
        : "+f"(d[0]), "+f"(d[1]), "+f"(d[2]), "+f"(d[3])
        : "r"(a[0]), "r"(a[1]), "r"(a[2]), "r"(a[3]), "r"(b[0]), "r"(b[1]));
}

// ---------------- prep: round + permute into fragment layout + norms ----------------
// 1024 blocks x 256 threads. Blocks [0,512): s (A layout); [512,1024): t (B layout).
__global__ void __launch_bounds__(256) prep_kernel(const float* __restrict__ s,
                                                   const float* __restrict__ t) {
    __shared__ float sm[16 * 516];
    int bid = blockIdx.x;
    bool is_s = (bid < 512);
    int blk = is_s ? bid : bid - 512;
    const float* src = (is_s ? s : t) + (size_t)blk * 16 * DIM;
    int tid = threadIdx.x;

    // coalesced load 16x512 floats
    #pragma unroll
    for (int it = 0; it < 8; it++) {
        int idx = it * 256 + tid;          // float4 index 0..2047
        int r = idx >> 7, c4 = idx & 127;
        float4 v = reinterpret_cast<const float4*>(src)[idx];
        *reinterpret_cast<float4*>(&sm[r * 516 + c4 * 4]) = v;
    }
    __syncthreads();

    // exact fp32 row norms: 8 warps, 2 rows each
    int w = tid >> 5, ln = tid & 31;
    float* sqout = (is_s ? g_s_sq : g_t_sq) + blk * 16;
    #pragma unroll
    for (int rr = 0; rr < 2; rr++) {
        int r = w * 2 + rr;
        float acc = 0.0f;
        #pragma unroll
        for (int j = 0; j < 16; j++) {
            float v = sm[r * 516 + ln + j * 32];
            acc += v * v;
        }
        #pragma unroll
        for (int o = 16; o > 0; o >>= 1) acc += __shfl_xor_sync(0xffffffffu, acc, o);
        if (ln == 0) sqout[r] = acc;
    }

    // permuted, tf32-rounded, coalesced writes
    if (is_s) {
        // A tile (16x8): elem (r,k) -> lane = (r&7)*4 + (k&3); e = (r>>3) | ((k>>2&1)<<1)
        float* dst = g_s32 + (size_t)blk * 8192;
        #pragma unroll
        for (int it = 0; it < 32; it++) {
            int o = it * 256 + tid;
            int kb = o >> 7, lane = (o >> 2) & 31, e = o & 3;
            int r = (lane >> 2) + ((e & 1) << 3);
            int k = kb * 8 + (lane & 3) + ((e >> 1) << 2);
            dst[o] = tf32_round(sm[r * 516 + k]);
        }
    } else {
        // B tile (8n x 8k): elem (k,n) -> lane = n*4 + (k&3); e = k>>2
        float* dst = g_t32 + (size_t)blk * 8192;   // 2 nb regions of 4096
        #pragma unroll
        for (int it = 0; it < 32; it++) {
            int o = it * 256 + tid;
            int nbl = o >> 12, oo = o & 4095;
            int kb = oo >> 6, lane = (oo >> 1) & 31, e = oo & 1;
            int r = nbl * 8 + (lane >> 2);
            int k = kb * 8 + (lane & 3) + (e << 2);
            dst[o] = tf32_round(sm[r * 516 + k]);
        }
    }
}

// ---------------- main GEMM kernel ----------------
__device__ __forceinline__ void load_stage(float* smbase, int stage,
                                           int rb_base, int nb_base,
                                           int kb_base, int tid) {
    float* As = smbase + stage * STAGE_F;
    float* Bs = As + A_STAGE_F;
    uint32_t a_base = smem_u32(As);
    uint32_t b_base = smem_u32(Bs);
    #pragma unroll
    for (int it = 0; it < 4; it++) {
        int c = it * 256 + tid;            // 0..1023 16B chunks
        int rb = c >> 7, rem = c & 127;
        const float* ga = g_s32 + (size_t)(rb_base + rb) * 8192 + kb_base * 128 + rem * 4;
        CP_ASYNC16(a_base + c * 16, ga);
        int nb = c >> 6, rem2 = c & 63;
        const float* gb = g_t32 + (size_t)(nb_base + nb) * 4096 + kb_base * 64 + rem2 * 4;
        CP_ASYNC16(b_base + c * 16, gb);
    }
}

__device__ __forceinline__ void load_frags(float4* a, float2* b,
                                           const float* As, const float* Bs,
                                           int ks, int l) {
    #pragma unroll
    for (int mt = 0; mt < 4; mt++)
        a[mt] = *reinterpret_cast<const float4*>(As + mt * 512 + ks * 128 + l * 4);
    #pragma unroll
    for (int nt = 0; nt < 4; nt++)
        b[nt] = *reinterpret_cast<const float2*>(Bs + nt * 256 + ks * 64 + l * 2);
}

__global__ void __launch_bounds__(256, 2) dist_kernel(float* __restrict__ out) {
    extern __shared__ float sm[];
    int tid = threadIdx.x;
    int wid = tid >> 5, l = tid & 31;
    int warp_m = wid & 1, warp_n = wid >> 1;   // 2 x 4 warps
    int wm0 = warp_m * 64, wn0 = warp_n * 32;  // warp tile 64(M) x 32(N)
    int rb_base = blockIdx.y * 8;
    int nb_base = blockIdx.x * 16;
    int bm = blockIdx.y * BM;
    int bn = blockIdx.x * BN;

    float acc[4][4][4];
    #pragma unroll
    for (int i = 0; i < 4; i++)
        #pragma unroll
        for (int j = 0; j < 4; j++)
            #pragma unroll
            for (int k = 0; k < 4; k++) acc[i][j][k] = 0.0f;

    load_stage(sm, 0, rb_base, nb_base, 0, tid); CP_COMMIT();
    load_stage(sm, 1, rb_base, nb_base, 4, tid); CP_COMMIT();

    float4 af[2][4];
    float2 bf[2][4];

    #pragma unroll 1
    for (int c = 0; c < NK; c++) {
        if (c == NK - 1) asm volatile("cp.async.wait_group 0;" ::: "memory");
        else             asm volatile("cp.async.wait_group 1;" ::: "memory");
        __syncthreads();
        if (c + 2 < NK) {
            load_stage(sm, (c + 2) % STAGES, rb_base, nb_base, (c + 2) * 4, tid);
            CP_COMMIT();
        }

        const float* As = sm + (c % STAGES) * STAGE_F + warp_m * 4 * 512;
        const float* Bs = sm + (c % STAGES) * STAGE_F + A_STAGE_F + warp_n * 4 * 256;

        // prime ks=0
        load_frags(af[0], bf[0], As, Bs, 0, l);

        #pragma unroll
        for (int ks = 0; ks < 4; ks++) {
            int cur = ks & 1;
            if (ks < 3)   // prefetch ks+1 while MMAs of ks issue
                load_frags(af[cur ^ 1], bf[cur ^ 1], As, Bs, ks + 1, l);
            #pragma unroll
            for (int mt = 0; mt < 4; mt++)
                #pragma unroll
                for (int nt = 0; nt < 4; nt++)
                    mma_tf32(acc[mt][nt],
                             reinterpret_cast<const uint32_t*>(&af[cur][mt]),
                             reinterpret_cast<const uint32_t*>(&bf[cur][nt]));
        }
    }

    // epilogue: dist = s_sq + t_sq - 2*cross
    int lr = l >> 2, lc = l & 3;
    #pragma unroll
    for (int mt = 0; mt < 4; mt++) {
        int r0 = bm + wm0 + mt * 16 + lr;
        float sq0 = __ldg(&g_s_sq[r0]);
        float sq1 = __ldg(&g_s_sq[r0 + 8]);
        #pragma unroll
        for (int nt = 0; nt < 4; nt++) {
            int cn = bn + wn0 + nt * 8 + lc * 2;
            float tq0 = __ldg(&g_t_sq[cn]);
            float tq1 = __ldg(&g_t_sq[cn + 1]);
            float2 o0, o1;
            o0.x = fmaf(-2.0f, acc[mt][nt][0], sq0 + tq0);
            o0.y = fmaf(-2.0f, acc[mt][nt][1], sq0 + tq1);
            o1.x = fmaf(-2.0f, acc[mt][nt][2], sq1 + tq0);
            o1.y = fmaf(-2.0f, acc[mt][nt][3], sq1 + tq1);
            *reinterpret_cast<float2*>(out + (size_t)r0 * NROWS + cn) = o0;
            *reinterpret_cast<float2*>(out + (size_t)(r0 + 8) * NROWS + cn) = o1;
        }
    }
}

// ---------------- launch ----------------
extern "C" void kernel_launch(void* const* d_in, const int* in_sizes, int n_in,
                              void* d_out, int out_size) {
    const float* s = (const float*)d_in[0];
    const float* t = (const float*)d_in[1];
    float* out = (float*)d_out;

    prep_kernel<<<1024, 256>>>(s, t);

    cudaFuncSetAttribute(dist_kernel, cudaFuncAttributeMaxDynamicSharedMemorySize,
                         SMEM_BYTES);
    dim3 grid(NROWS / BN, NROWS / BM);   // 64 x 64
    dist_kernel<<<grid, 256, SMEM_BYTES>>>(out);
}

// round 16
// speedup vs baseline: 1.0928x; 1.0928x over previous
#include <cuda_runtime.h>
#include <cuda_bf16.h>
#include <cstdint>

#define NROWS 8192
#define DIM   512
#define BM    128
#define BN    128
#define BK    32
#define NK    (DIM / BK)          // 16 k-chunks
#define STAGES 3
// Fragment-permuted tiles (both operands lane-major, 16B per lane):
//  A: [rb(16 rows)][kb(8 k)]: 128 floats, lane*4 contiguous (a0..a3)
//  B: [pair(16 cols)][kb(8 k)]: 128 floats, lane*4 = {n,k},{n,k+4},{n+8,k},{n+8,k+4}
#define A_STAGE_F 4096            // 8 rb * 4 kb * 128
#define B_STAGE_F 4096            // 8 pair * 4 kb * 128
#define STAGE_F   (A_STAGE_F + B_STAGE_F)
#define SMEM_BYTES (STAGES * STAGE_F * 4)   // 98304

// ---------------- device scratch (static, allocation-free) ----------------
__device__ float g_s32[NROWS * DIM];   // s: A-permuted [512 rb][64 kb][128]
__device__ float g_t32[NROWS * DIM];   // t: B-pair-permuted [512 pair][64 kb][128]
__device__ float g_s_sq[NROWS];
__device__ float g_t_sq[NROWS];

// ---------------- helpers ----------------
__device__ __forceinline__ uint32_t smem_u32(const void* p) {
    uint32_t a;
    asm("{ .reg .u64 t; cvta.to.shared.u64 t, %1; cvt.u32.u64 %0, t; }"
        : "=r"(a) : "l"(p));
    return a;
}

__device__ __forceinline__ float tf32_round(float x) {
    uint32_t u;
    asm("cvt.rna.tf32.f32 %0, %1;" : "=r"(u) : "f"(x));
    return __uint_as_float(u);
}

#define CP_ASYNC16(smem_addr, gptr)                                           \
    asm volatile("cp.async.cg.shared.global [%0], [%1], 16;"                  \
                 :: "r"(smem_addr), "l"(gptr) : "memory")
#define CP_COMMIT() asm volatile("cp.async.commit_group;" ::: "memory")

__device__ __forceinline__ void mma_tf32(float* d, const uint32_t* a,
                                         uint32_t b0, uint32_t b1) {
    asm volatile(
        "mma.sync.aligned.m16n8k8.row.col.f32.tf32.tf32.f32 "
        "{%0,%1,%2,%3}, {%4,%5,%6,%7}, {%8,%9}, {%0,%1,%2,%3};"
        : "+f"(d[0]), "+f"(d[1]), "+f"(d[2]), "+f"(d[3])
        : "r"(a[0]), "r"(a[1]), "r"(a[2]), "r"(a[3]), "r"(b0), "r"(b1));
}

// ---------------- prep: round + permute into fragment layout + norms ----------------
// 1024 blocks x 256 threads. Blocks [0,512): s (A layout); [512,1024): t (B-pair layout).
// Each block: 16 rows x 512 cols staged through smem.
__global__ void __launch_bounds__(256) prep_kernel(const float* __restrict__ s,
                                                   const float* __restrict__ t) {
    __shared__ float sm[16 * 516];
    int bid = blockIdx.x;
    bool is_s = (bid < 512);
    int blk = is_s ? bid : bid - 512;
    const float* src = (is_s ? s : t) + (size_t)blk * 16 * DIM;
    int tid = threadIdx.x;

    #pragma unroll
    for (int it = 0; it < 8; it++) {
        int idx = it * 256 + tid;          // float4 index 0..2047
        int r = idx >> 7, c4 = idx & 127;
        float4 v = reinterpret_cast<const float4*>(src)[idx];
        *reinterpret_cast<float4*>(&sm[r * 516 + c4 * 4]) = v;
    }
    __syncthreads();

    // exact fp32 row norms: 8 warps, 2 rows each
    int w = tid >> 5, ln = tid & 31;
    float* sqout = (is_s ? g_s_sq : g_t_sq) + blk * 16;
    #pragma unroll
    for (int rr = 0; rr < 2; rr++) {
        int r = w * 2 + rr;
        float acc = 0.0f;
        #pragma unroll
        for (int j = 0; j < 16; j++) {
            float v = sm[r * 516 + ln + j * 32];
            acc += v * v;
        }
        #pragma unroll
        for (int o = 16; o > 0; o >>= 1) acc += __shfl_xor_sync(0xffffffffu, acc, o);
        if (ln == 0) sqout[r] = acc;
    }

    if (is_s) {
        // A: (r,k) -> lane = (r&7)*4 + (k&3); e = (r>>3) | ((k>>2&1)<<1)
        float* dst = g_s32 + (size_t)blk * 8192;
        #pragma unroll
        for (int it = 0; it < 32; it++) {
            int o = it * 256 + tid;
            int kb = o >> 7, lane = (o >> 2) & 31, e = o & 3;
            int r = (lane >> 2) + ((e & 1) << 3);
            int k = kb * 8 + (lane & 3) + ((e >> 1) << 2);
            dst[o] = tf32_round(sm[r * 516 + k]);
        }
    } else {
        // B-pair: block's 16 rows (= n values) form one pair.
        // 16B per lane: e2=0: (n_lo,k), e2=1: (n_lo,k+4), e2=2: (n_hi,k), e2=3: (n_hi,k+4)
        // n_lo = lane>>2, n_hi = n_lo + 8, k = kb*8 + (lane&3)
        float* dst = g_t32 + (size_t)blk * 8192;
        #pragma unroll
        for (int it = 0; it < 32; it++) {
            int o = it * 256 + tid;
            int kb = o >> 7, lane = (o >> 2) & 31, e2 = o & 3;
            int r = (lane >> 2) + ((e2 >> 1) << 3);
            int k = kb * 8 + (lane & 3) + ((e2 & 1) << 2);
            dst[o] = tf32_round(sm[r * 516 + k]);
        }
    }
}

// ---------------- main GEMM kernel ----------------
// 128 threads, 2x2 warps, warp tile 64(M) x 64(N)
__device__ __forceinline__ void load_stage(float* smbase, int stage,
                                           int rb_base, int pr_base,
                                           int kb_base, int tid) {
    float* As = smbase + stage * STAGE_F;
    float* Bs = As + A_STAGE_F;
    uint32_t a_base = smem_u32(As);
    uint32_t b_base = smem_u32(Bs);
    #pragma unroll
    for (int it = 0; it < 8; it++) {
        int c = it * 128 + tid;            // 0..1023 16B chunks
        int blkid = c >> 7, rem = c & 127; // 8 blocks x 512 floats each
        const float* ga = g_s32 + (size_t)(rb_base + blkid) * 8192 + kb_base * 128 + rem * 4;
        CP_ASYNC16(a_base + c * 16, ga);
        const float* gb = g_t32 + (size_t)(pr_base + blkid) * 8192 + kb_base * 128 + rem * 4;
        CP_ASYNC16(b_base + c * 16, gb);
    }
}

__global__ void __launch_bounds__(128, 2) dist_kernel(float* __restrict__ out) {
    extern __shared__ float sm[];
    int tid = threadIdx.x;
    int wid = tid >> 5, l = tid & 31;
    int warp_m = wid & 1, warp_n = wid >> 1;   // 2 x 2 warps
    int rb_base = blockIdx.y * 8;
    int pr_base = blockIdx.x * 8;
    int bm = blockIdx.y * BM;
    int bn = blockIdx.x * BN;

    float acc[4][8][4];
    #pragma unroll
    for (int i = 0; i < 4; i++)
        #pragma unroll
        for (int j = 0; j < 8; j++)
            #pragma unroll
            for (int k = 0; k < 4; k++) acc[i][j][k] = 0.0f;

    load_stage(sm, 0, rb_base, pr_base, 0, tid); CP_COMMIT();
    load_stage(sm, 1, rb_base, pr_base, 4, tid); CP_COMMIT();

    #pragma unroll 1
    for (int c = 0; c < NK; c++) {
        if (c == NK - 1) asm volatile("cp.async.wait_group 0;" ::: "memory");
        else             asm volatile("cp.async.wait_group 1;" ::: "memory");
        __syncthreads();
        if (c + 2 < NK) {
            load_stage(sm, (c + 2) % STAGES, rb_base, pr_base, (c + 2) * 4, tid);
            CP_COMMIT();
        }

        const float* As = sm + (c % STAGES) * STAGE_F + warp_m * 4 * 512;
        const float* Bs = sm + (c % STAGES) * STAGE_F + A_STAGE_F + warp_n * 4 * 512;

        #pragma unroll
        for (int ks = 0; ks < 4; ks++) {
            float4 a[4], bb[4];
            #pragma unroll
            for (int mt = 0; mt < 4; mt++)
                a[mt] = *reinterpret_cast<const float4*>(As + mt * 512 + ks * 128 + l * 4);
            #pragma unroll
            for (int j = 0; j < 4; j++)
                bb[j] = *reinterpret_cast<const float4*>(Bs + j * 512 + ks * 128 + l * 4);
            #pragma unroll
            for (int mt = 0; mt < 4; mt++)
                #pragma unroll
                for (int j = 0; j < 4; j++) {
                    mma_tf32(acc[mt][2 * j],
                             reinterpret_cast<const uint32_t*>(&a[mt]),
                             __float_as_uint(bb[j].x), __float_as_uint(bb[j].y));
                    mma_tf32(acc[mt][2 * j + 1],
                             reinterpret_cast<const uint32_t*>(&a[mt]),
                             __float_as_uint(bb[j].z), __float_as_uint(bb[j].w));
                }
        }
    }

    // epilogue: dist = s_sq + t_sq - 2*cross
    int lr = l >> 2, lc = l & 3;
    #pragma unroll
    for (int mt = 0; mt < 4; mt++) {
        int r0 = bm + warp_m * 64 + mt * 16 + lr;
        float sq0 = __ldg(&g_s_sq[r0]);
        float sq1 = __ldg(&g_s_sq[r0 + 8]);
        #pragma unroll
        for (int nt = 0; nt < 8; nt++) {
            int cn = bn + warp_n * 64 + (nt >> 1) * 16 + (nt & 1) * 8 + lc * 2;
            float tq0 = __ldg(&g_t_sq[cn]);
            float tq1 = __ldg(&g_t_sq[cn + 1]);
            float2 o0, o1;
            o0.x = fmaf(-2.0f, acc[mt][nt][0], sq0 + tq0);
            o0.y = fmaf(-2.0f, acc[mt][nt][1], sq0 + tq1);
            o1.x = fmaf(-2.0f, acc[mt][nt][2], sq1 + tq0);
            o1.y = fmaf(-2.0f, acc[mt][nt][3], sq1 + tq1);
            *reinterpret_cast<float2*>(out + (size_t)r0 * NROWS + cn) = o0;
            *reinterpret_cast<float2*>(out + (size_t)(r0 + 8) * NROWS + cn) = o1;
        }
    }
}

// ---------------- launch ----------------
extern "C" void kernel_launch(void* const* d_in, const int* in_sizes, int n_in,
                              void* d_out, int out_size) {
    const float* s = (const float*)d_in[0];
    const float* t = (const float*)d_in[1];
    float* out = (float*)d_out;

    prep_kernel<<<1024, 256>>>(s, t);

    cudaFuncSetAttribute(dist_kernel, cudaFuncAttributeMaxDynamicSharedMemorySize,
                         SMEM_BYTES);
    dim3 grid(NROWS / BN, NROWS / BM);   // 64 x 64
    dist_kernel<<<grid, 128, SMEM_BYTES>>>(out);
}

// round 17
// speedup vs baseline: 1.1791x; 1.0789x over previous
#include <cuda_runtime.h>
#include <cuda_bf16.h>
#include <cstdint>

#define NROWS 8192
#define DIM   512
#define BM    128
#define BN    128
#define BK    32
#define NK    (DIM / BK)          // 16 k-chunks
#define STAGES 2
// Fragment-permuted tiles (both operands lane-major, 16B per lane):
//  A: [rb(16 rows)][kb(8 k)]: 128 floats, lane*4 contiguous (a0..a3)
//  B: [pair(16 cols)][kb(8 k)]: 128 floats, lane*4 = {n,k},{n,k+4},{n+8,k},{n+8,k+4}
#define A_STAGE_F 4096            // 8 rb * 4 kb * 128
#define B_STAGE_F 4096            // 8 pair * 4 kb * 128
#define STAGE_F   (A_STAGE_F + B_STAGE_F)
#define SMEM_BYTES (STAGES * STAGE_F * 4)   // 65536 -> 3 CTAs/SM fits 192KB

// ---------------- device scratch (static, allocation-free) ----------------
__device__ float g_s32[NROWS * DIM];   // s: A-permuted [512 rb][64 kb][128]
__device__ float g_t32[NROWS * DIM];   // t: B-pair-permuted [512 pair][64 kb][128]
__device__ float g_s_sq[NROWS];
__device__ float g_t_sq[NROWS];

// ---------------- helpers ----------------
__device__ __forceinline__ uint32_t smem_u32(const void* p) {
    uint32_t a;
    asm("{ .reg .u64 t; cvta.to.shared.u64 t, %1; cvt.u32.u64 %0, t; }"
        : "=r"(a) : "l"(p));
    return a;
}

__device__ __forceinline__ float tf32_round(float x) {
    uint32_t u;
    asm("cvt.rna.tf32.f32 %0, %1;" : "=r"(u) : "f"(x));
    return __uint_as_float(u);
}

#define CP_ASYNC16(smem_addr, gptr)                                           \
    asm volatile("cp.async.cg.shared.global [%0], [%1], 16;"                  \
                 :: "r"(smem_addr), "l"(gptr) : "memory")
#define CP_COMMIT() asm volatile("cp.async.commit_group;" ::: "memory")

__device__ __forceinline__ void mma_tf32(float* d, const uint32_t* a,
                                         uint32_t b0, uint32_t b1) {
    asm volatile(
        "mma.sync.aligned.m16n8k8.row.col.f32.tf32.tf32.f32 "
        "{%0,%1,%2,%3}, {%4,%5,%6,%7}, {%8,%9}, {%0,%1,%2,%3};"
        : "+f"(d[0]), "+f"(d[1]), "+f"(d[2]), "+f"(d[3])
        : "r"(a[0]), "r"(a[1]), "r"(a[2]), "r"(a[3]), "r"(b0), "r"(b1));
}

// ---------------- prep: round + permute into fragment layout + norms ----------------
// 1024 blocks x 256 threads. Blocks [0,512): s (A layout); [512,1024): t (B-pair layout).
__global__ void __launch_bounds__(256) prep_kernel(const float* __restrict__ s,
                                                   const float* __restrict__ t) {
    __shared__ float sm[16 * 516];
    int bid = blockIdx.x;
    bool is_s = (bid < 512);
    int blk = is_s ? bid : bid - 512;
    const float* src = (is_s ? s : t) + (size_t)blk * 16 * DIM;
    int tid = threadIdx.x;

    #pragma unroll
    for (int it = 0; it < 8; it++) {
        int idx = it * 256 + tid;          // float4 index 0..2047
        int r = idx >> 7, c4 = idx & 127;
        float4 v = reinterpret_cast<const float4*>(src)[idx];
        *reinterpret_cast<float4*>(&sm[r * 516 + c4 * 4]) = v;
    }
    __syncthreads();

    // exact fp32 row norms: 8 warps, 2 rows each
    int w = tid >> 5, ln = tid & 31;
    float* sqout = (is_s ? g_s_sq : g_t_sq) + blk * 16;
    #pragma unroll
    for (int rr = 0; rr < 2; rr++) {
        int r = w * 2 + rr;
        float acc = 0.0f;
        #pragma unroll
        for (int j = 0; j < 16; j++) {
            float v = sm[r * 516 + ln + j * 32];
            acc += v * v;
        }
        #pragma unroll
        for (int o = 16; o > 0; o >>= 1) acc += __shfl_xor_sync(0xffffffffu, acc, o);
        if (ln == 0) sqout[r] = acc;
    }

    if (is_s) {
        // A: (r,k) -> lane = (r&7)*4 + (k&3); e = (r>>3) | ((k>>2&1)<<1)
        float* dst = g_s32 + (size_t)blk * 8192;
        #pragma unroll
        for (int it = 0; it < 32; it++) {
            int o = it * 256 + tid;
            int kb = o >> 7, lane = (o >> 2) & 31, e = o & 3;
            int r = (lane >> 2) + ((e & 1) << 3);
            int k = kb * 8 + (lane & 3) + ((e >> 1) << 2);
            dst[o] = tf32_round(sm[r * 516 + k]);
        }
    } else {
        // B-pair: e2=0:(n_lo,k) e2=1:(n_lo,k+4) e2=2:(n_hi,k) e2=3:(n_hi,k+4)
        float* dst = g_t32 + (size_t)blk * 8192;
        #pragma unroll
        for (int it = 0; it < 32; it++) {
            int o = it * 256 + tid;
            int kb = o >> 7, lane = (o >> 2) & 31, e2 = o & 3;
            int r = (lane >> 2) + ((e2 >> 1) << 3);
            int k = kb * 8 + (lane & 3) + ((e2 & 1) << 2);
            dst[o] = tf32_round(sm[r * 516 + k]);
        }
    }
}

// ---------------- main GEMM kernel ----------------
// 128 threads, 2x2 warps, warp tile 64(M) x 64(N), 2-stage pipeline, 3 CTAs/SM
__device__ __forceinline__ void load_stage(float* smbase, int stage,
                                           int rb_base, int pr_base,
                                           int kb_base, int tid) {
    float* As = smbase + stage * STAGE_F;
    float* Bs = As + A_STAGE_F;
    uint32_t a_base = smem_u32(As);
    uint32_t b_base = smem_u32(Bs);
    #pragma unroll
    for (int it = 0; it < 8; it++) {
        int c = it * 128 + tid;            // 0..1023 16B chunks
        int blkid = c >> 7, rem = c & 127; // 8 blocks x 512 floats each
        const float* ga = g_s32 + (size_t)(rb_base + blkid) * 8192 + kb_base * 128 + rem * 4;
        CP_ASYNC16(a_base + c * 16, ga);
        const float* gb = g_t32 + (size_t)(pr_base + blkid) * 8192 + kb_base * 128 + rem * 4;
        CP_ASYNC16(b_base + c * 16, gb);
    }
}

__global__ void __launch_bounds__(128, 3) dist_kernel(float* __restrict__ out) {
    extern __shared__ float sm[];
    int tid = threadIdx.x;
    int wid = tid >> 5, l = tid & 31;
    int warp_m = wid & 1, warp_n = wid >> 1;   // 2 x 2 warps
    int rb_base = blockIdx.y * 8;
    int pr_base = blockIdx.x * 8;
    int bm = blockIdx.y * BM;
    int bn = blockIdx.x * BN;

    float acc[4][8][4];
    #pragma unroll
    for (int i = 0; i < 4; i++)
        #pragma unroll
        for (int j = 0; j < 8; j++)
            #pragma unroll
            for (int k = 0; k < 4; k++) acc[i][j][k] = 0.0f;

    load_stage(sm, 0, rb_base, pr_base, 0, tid); CP_COMMIT();

    #pragma unroll 1
    for (int c = 0; c < NK; c++) {
        asm volatile("cp.async.wait_group 0;" ::: "memory");
        __syncthreads();
        if (c + 1 < NK) {
            load_stage(sm, (c + 1) & 1, rb_base, pr_base, (c + 1) * 4, tid);
            CP_COMMIT();
        }

        const float* As = sm + (c & 1) * STAGE_F + warp_m * 4 * 512;
        const float* Bs = sm + (c & 1) * STAGE_F + A_STAGE_F + warp_n * 4 * 512;

        #pragma unroll
        for (int ks = 0; ks < 4; ks++) {
            float4 a[4];
            #pragma unroll
            for (int mt = 0; mt < 4; mt++)
                a[mt] = *reinterpret_cast<const float4*>(As + mt * 512 + ks * 128 + l * 4);
            // stream B one float4 at a time: 1 LDS.128 -> 8 MMAs, low live regs
            #pragma unroll
            for (int j = 0; j < 4; j++) {
                float4 bb = *reinterpret_cast<const float4*>(Bs + j * 512 + ks * 128 + l * 4);
                #pragma unroll
                for (int mt = 0; mt < 4; mt++) {
                    mma_tf32(acc[mt][2 * j],
                             reinterpret_cast<const uint32_t*>(&a[mt]),
                             __float_as_uint(bb.x), __float_as_uint(bb.y));
                    mma_tf32(acc[mt][2 * j + 1],
                             reinterpret_cast<const uint32_t*>(&a[mt]),
                             __float_as_uint(bb.z), __float_as_uint(bb.w));
                }
            }
        }
        __syncthreads();   // protect stage reuse before next iteration's writes
    }

    // epilogue: dist = s_sq + t_sq - 2*cross
    int lr = l >> 2, lc = l & 3;
    #pragma unroll
    for (int mt = 0; mt < 4; mt++) {
        int r0 = bm + warp_m * 64 + mt * 16 + lr;
        float sq0 = __ldg(&g_s_sq[r0]);
        float sq1 = __ldg(&g_s_sq[r0 + 8]);
        #pragma unroll
        for (int nt = 0; nt < 8; nt++) {
            int cn = bn + warp_n * 64 + (nt >> 1) * 16 + (nt & 1) * 8 + lc * 2;
            float tq0 = __ldg(&g_t_sq[cn]);
            float tq1 = __ldg(&g_t_sq[cn + 1]);
            float2 o0, o1;
            o0.x = fmaf(-2.0f, acc[mt][nt][0], sq0 + tq0);
            o0.y = fmaf(-2.0f, acc[mt][nt][1], sq0 + tq1);
            o1.x = fmaf(-2.0f, acc[mt][nt][2], sq1 + tq0);
            o1.y = fmaf(-2.0f, acc[mt][nt][3], sq1 + tq1);
            *reinterpret_cast<float2*>(out + (size_t)r0 * NROWS + cn) = o0;
            *reinterpret_cast<float2*>(out + (size_t)(r0 + 8) * NROWS + cn) = o1;
        }
    }
}

// ---------------- launch ----------------
extern "C" void kernel_launch(void* const* d_in, const int* in_sizes, int n_in,
                              void* d_out, int out_size) {
    const float* s = (const float*)d_in[0];
    const float* t = (const float*)d_in[1];
    float* out = (float*)d_out;

    prep_kernel<<<1024, 256>>>(s, t);

    cudaFuncSetAttribute(dist_kernel, cudaFuncAttributeMaxDynamicSharedMemorySize,
                         SMEM_BYTES);
    dim3 grid(NROWS / BN, NROWS / BM);   // 64 x 64
    dist_kernel<<<grid, 128, SMEM_BYTES>>>(out);
}